// round 3
// baseline (speedup 1.0000x reference)
#include <cuda_runtime.h>
#include <cuda_fp16.h>

#define NB   64
#define NIC  2048
#define NOC  32
#define ND   16
#define ROWH 24   // halves per padded smem row (48B stride -> conflict-free LDS.128 phases)

// u_hat scratch in fp16, layout [b][o][i][d]: each (b,o) routing slice = 64KB contiguous.
__device__ __half g_uhat[(long)NB * NOC * NIC * ND];   // 128 MiB

// ---------------------------------------------------------------------------
// Kernel 1: u_hat[b,o,i,d] = sum_m W[i,o,d,m] * x[b,i,m], stored fp16.
// grid = (32 i-chunks of 64, 32 o), block = 256 = 64 i_local x 4 d-quads.
// ---------------------------------------------------------------------------
__global__ __launch_bounds__(256) void uhat_kernel(const float* __restrict__ x,
                                                   const float* __restrict__ W) {
    __shared__ float4 xs[2048];   // [bb 16][i_off 64][mh 2] = 32KB
    const int t  = threadIdx.x;
    const int ic = blockIdx.x;
    const int o  = blockIdx.y;
    const int il = t >> 2;
    const int q  = t & 3;
    const int i  = ic * 64 + il;

    const float4* W4 = (const float4*)W;
    float4 wA[4], wB[4];
#pragma unroll
    for (int dd = 0; dd < 4; dd++) {
        int d = q * 4 + dd;
        long base = (((long)i * NOC + o) * ND + d) * 2;
        wA[dd] = W4[base];
        wB[dd] = W4[base + 1];
    }

    const float4* x4 = (const float4*)x;
    uint2* U2 = (uint2*)g_uhat;   // 8B = 4 halves per store

    for (int bc = 0; bc < 4; bc++) {
        const int b0 = bc * 16;
        __syncthreads();
#pragma unroll
        for (int j = 0; j < 8; j++) {
            int f  = t + 256 * j;
            int bb = f >> 7;
            int r  = f & 127;
            xs[f] = x4[((long)(b0 + bb) * NIC + ic * 64 + (r >> 1)) * 2 + (r & 1)];
        }
        __syncthreads();
#pragma unroll 4
        for (int bb = 0; bb < 16; bb++) {
            float4 xa = xs[bb * 128 + il * 2];
            float4 xb = xs[bb * 128 + il * 2 + 1];
            float acc[4];
#pragma unroll
            for (int dd = 0; dd < 4; dd++) {
                acc[dd] = wA[dd].x * xa.x + wA[dd].y * xa.y + wA[dd].z * xa.z + wA[dd].w * xa.w
                        + wB[dd].x * xb.x + wB[dd].y * xb.y + wB[dd].z * xb.z + wB[dd].w * xb.w;
            }
            __half2 h01 = __floats2half2_rn(acc[0], acc[1]);
            __half2 h23 = __floats2half2_rn(acc[2], acc[3]);
            uint2 val;
            val.x = *(unsigned int*)&h01;
            val.y = *(unsigned int*)&h23;
            U2[(((long)(b0 + bb) * NOC + o) * NIC + i) * 4 + q] = val;
        }
    }
}

// ---------------------------------------------------------------------------
// Kernel 2: full dynamic routing, one (b,o) pair per CTA. fp16 slice in smem
// (2048 rows x 24-half padded rows = 96KB -> 2 CTAs/SM). Scan 1 fused into
// the global load; iterations 2,3 are single fused SMEM scans each.
// ---------------------------------------------------------------------------
__global__ __launch_bounds__(256, 2) void route_kernel(float* __restrict__ out) {
    extern __shared__ __align__(16) __half su[];   // [NIC][ROWH] = 98304 B
    __shared__ float red[8 * 20];
    __shared__ float fin[20];

    const int t    = threadIdx.x;
    const int bo   = blockIdx.x;
    const int warp = t >> 5;
    const int lane = t & 31;

    const uint4* U = (const uint4*)g_uhat + (long)bo * (NIC * 2);   // 2 uint4 per row

    // ---- load slice (fp16) + fused scan 1 (uniform c => plain sum over i) ----
    float s[16];
#pragma unroll
    for (int d = 0; d < 16; d++) s[d] = 0.f;

#pragma unroll
    for (int j = 0; j < 8; j++) {
        const int i = t + 256 * j;
        uint4 r0 = U[i * 2];
        uint4 r1 = U[i * 2 + 1];
        *(uint4*)&su[i * ROWH]     = r0;
        *(uint4*)&su[i * ROWH + 8] = r1;
        const __half2* h0 = (const __half2*)&r0;
        const __half2* h1 = (const __half2*)&r1;
#pragma unroll
        for (int p = 0; p < 4; p++) {
            float2 f0 = __half22float2(h0[p]);
            float2 f1 = __half22float2(h1[p]);
            s[2 * p]     += f0.x;
            s[2 * p + 1] += f0.y;
            s[8 + 2 * p]     += f1.x;
            s[8 + 2 * p + 1] += f1.y;
        }
    }
    // block reduce 16 values
#pragma unroll
    for (int off = 16; off >= 1; off >>= 1)
#pragma unroll
        for (int d = 0; d < 16; d++) s[d] += __shfl_down_sync(0xffffffffu, s[d], off);
    if (lane == 0)
#pragma unroll
        for (int d = 0; d < 16; d++) red[warp * 20 + d] = s[d];
    __syncthreads();
    if (t < 16) {
        float ss = 0.f;
#pragma unroll
        for (int w = 0; w < 8; w++) ss += red[w * 20 + t];
        fin[t] = ss;
    }
    __syncthreads();

    // v1 = squash(mean_i u) — computed redundantly by all threads into registers
    float v[16];
    {
        float sq = 0.f;
#pragma unroll
        for (int d = 0; d < 16; d++) {
            float sd = fin[d] * (1.0f / (float)NIC);
            v[d] = sd;
            sq += sd * sd;
        }
        float scale = sq / ((1.0f + sq) * sqrtf(sq + 1e-9f));
#pragma unroll
        for (int d = 0; d < 16; d++) v[d] *= scale;
    }

    float bl[8];
#pragma unroll
    for (int k = 0; k < 8; k++) bl[k] = 0.f;

    __syncthreads();   // slice fully staged before scan phase (also red/fin reuse)

    // ---- iterations 2 and 3: one fused SMEM scan each ----
#pragma unroll
    for (int iter = 0; iter < 2; iter++) {
#pragma unroll
        for (int d = 0; d < 16; d++) s[d] = 0.f;
        float Z = 0.f;
#pragma unroll
        for (int k = 0; k < 8; k++) {
            const __half* row = &su[(t + 256 * k) * ROWH];
            uint4 r0 = *(const uint4*)(row);
            uint4 r1 = *(const uint4*)(row + 8);
            const __half2* h0 = (const __half2*)&r0;
            const __half2* h1 = (const __half2*)&r1;
            float uf[16];
#pragma unroll
            for (int p = 0; p < 4; p++) {
                float2 f0 = __half22float2(h0[p]);
                float2 f1 = __half22float2(h1[p]);
                uf[2 * p]         = f0.x;
                uf[2 * p + 1]     = f0.y;
                uf[8 + 2 * p]     = f1.x;
                uf[8 + 2 * p + 1] = f1.y;
            }
            float dot = 0.f;
#pragma unroll
            for (int d = 0; d < 16; d++) dot += uf[d] * v[d];
            float b = bl[k] + dot;
            bl[k] = b;
            float e = __expf(b);   // b-logits bounded ~|1|, no max-subtraction needed
            Z += e;
#pragma unroll
            for (int d = 0; d < 16; d++) s[d] += e * uf[d];
        }
        // block reduce 17 values
#pragma unroll
        for (int off = 16; off >= 1; off >>= 1) {
#pragma unroll
            for (int d = 0; d < 16; d++) s[d] += __shfl_down_sync(0xffffffffu, s[d], off);
            Z += __shfl_down_sync(0xffffffffu, Z, off);
        }
        if (lane == 0) {
#pragma unroll
            for (int d = 0; d < 16; d++) red[warp * 20 + d] = s[d];
            red[warp * 20 + 16] = Z;
        }
        __syncthreads();
        if (t < 17) {
            float ss = 0.f;
#pragma unroll
            for (int w = 0; w < 8; w++) ss += red[w * 20 + t];
            fin[t] = ss;
        }
        __syncthreads();

        float inv = 1.0f / fin[16];
        float sq = 0.f;
        float sloc[16];
#pragma unroll
        for (int d = 0; d < 16; d++) {
            sloc[d] = fin[d] * inv;
            sq += sloc[d] * sloc[d];
        }
        float scale = sq / ((1.0f + sq) * sqrtf(sq + 1e-9f));
        if (iter == 1) {
            if (t < 16) out[bo * 16 + t] = sloc[t] * scale;
        } else {
#pragma unroll
            for (int d = 0; d < 16; d++) v[d] = sloc[d] * scale;
        }
        __syncthreads();
    }
}

// ---------------------------------------------------------------------------
extern "C" void kernel_launch(void* const* d_in, const int* in_sizes, int n_in,
                              void* d_out, int out_size) {
    (void)in_sizes; (void)n_in; (void)out_size;
    const float* x = (const float*)d_in[0];   // [64, 2048, 8]
    const float* W = (const float*)d_in[1];   // [1, 2048, 32, 16, 8]
    float* out = (float*)d_out;               // [64, 32, 16]

    uhat_kernel<<<dim3(NIC / 64, NOC), 256>>>(x, W);

    const int smem = NIC * ROWH * (int)sizeof(__half);   // 98304 B
    cudaFuncSetAttribute(route_kernel, cudaFuncAttributeMaxDynamicSharedMemorySize, smem);
    route_kernel<<<NB * NOC, 256, smem>>>(out);
}

// round 4
// speedup vs baseline: 1.0051x; 1.0051x over previous
#include <cuda_runtime.h>
#include <cuda_fp16.h>

#define NB   64
#define NIC  2048
#define NOC  32
#define ND   16
#define ROWH 24   // halves per padded smem row (48B stride -> conflict-free LDS.128 phases)

// u_hat scratch in fp16, layout [b][o][i][d]: each (b,o) routing slice = 64KB contiguous.
__device__ __half g_uhat[(long)NB * NOC * NIC * ND];   // 128 MiB

// ---------------------------------------------------------------------------
// Kernel 1: u_hat[b,o,i,d] = sum_m W[i,o,d,m] * x[b,i,m], stored fp16.
// grid = (32 i-chunks of 64, 32 o), block = 256 = 64 i_local x 4 d-quads.
// ---------------------------------------------------------------------------
__global__ __launch_bounds__(256) void uhat_kernel(const float* __restrict__ x,
                                                   const float* __restrict__ W) {
    __shared__ float4 xs[2048];   // [bb 16][i_off 64][mh 2] = 32KB
    const int t  = threadIdx.x;
    const int ic = blockIdx.x;
    const int o  = blockIdx.y;
    const int il = t >> 2;
    const int q  = t & 3;
    const int i  = ic * 64 + il;

    const float4* W4 = (const float4*)W;
    float4 wA[4], wB[4];
#pragma unroll
    for (int dd = 0; dd < 4; dd++) {
        int d = q * 4 + dd;
        long base = (((long)i * NOC + o) * ND + d) * 2;
        wA[dd] = W4[base];
        wB[dd] = W4[base + 1];
    }

    const float4* x4 = (const float4*)x;
    uint2* U2 = (uint2*)g_uhat;   // 8B = 4 halves per store

    for (int bc = 0; bc < 4; bc++) {
        const int b0 = bc * 16;
        __syncthreads();
#pragma unroll
        for (int j = 0; j < 8; j++) {
            int f  = t + 256 * j;
            int bb = f >> 7;
            int r  = f & 127;
            xs[f] = x4[((long)(b0 + bb) * NIC + ic * 64 + (r >> 1)) * 2 + (r & 1)];
        }
        __syncthreads();
#pragma unroll 4
        for (int bb = 0; bb < 16; bb++) {
            float4 xa = xs[bb * 128 + il * 2];
            float4 xb = xs[bb * 128 + il * 2 + 1];
            float acc[4];
#pragma unroll
            for (int dd = 0; dd < 4; dd++) {
                acc[dd] = wA[dd].x * xa.x + wA[dd].y * xa.y + wA[dd].z * xa.z + wA[dd].w * xa.w
                        + wB[dd].x * xb.x + wB[dd].y * xb.y + wB[dd].z * xb.z + wB[dd].w * xb.w;
            }
            __half2 h01 = __floats2half2_rn(acc[0], acc[1]);
            __half2 h23 = __floats2half2_rn(acc[2], acc[3]);
            uint2 val;
            val.x = *(unsigned int*)&h01;
            val.y = *(unsigned int*)&h23;
            U2[(((long)(b0 + bb) * NOC + o) * NIC + i) * 4 + q] = val;
        }
    }
}

// ---------------------------------------------------------------------------
// Kernel 2: full dynamic routing, one (b,o) pair per CTA. fp16 slice in smem
// (2048 rows x 24-half padded rows = 96KB -> 2 CTAs/SM). Scan 1 fused into
// the global load; iterations 2,3 are single fused SMEM scans each.
// ---------------------------------------------------------------------------
__global__ __launch_bounds__(256, 2) void route_kernel(float* __restrict__ out) {
    extern __shared__ __align__(16) __half su[];   // [NIC][ROWH] = 98304 B
    __shared__ float red[8 * 20];
    __shared__ float fin[20];

    const int t    = threadIdx.x;
    const int bo   = blockIdx.x;
    const int warp = t >> 5;
    const int lane = t & 31;

    const uint4* U = (const uint4*)g_uhat + (long)bo * (NIC * 2);   // 2 uint4 per row

    // ---- load slice (fp16) + fused scan 1 (uniform c => plain sum over i) ----
    float s[16];
#pragma unroll
    for (int d = 0; d < 16; d++) s[d] = 0.f;

#pragma unroll
    for (int j = 0; j < 8; j++) {
        const int i = t + 256 * j;
        uint4 r0 = U[i * 2];
        uint4 r1 = U[i * 2 + 1];
        *(uint4*)&su[i * ROWH]     = r0;
        *(uint4*)&su[i * ROWH + 8] = r1;
        const __half2* h0 = (const __half2*)&r0;
        const __half2* h1 = (const __half2*)&r1;
#pragma unroll
        for (int p = 0; p < 4; p++) {
            float2 f0 = __half22float2(h0[p]);
            float2 f1 = __half22float2(h1[p]);
            s[2 * p]     += f0.x;
            s[2 * p + 1] += f0.y;
            s[8 + 2 * p]     += f1.x;
            s[8 + 2 * p + 1] += f1.y;
        }
    }
    // block reduce 16 values
#pragma unroll
    for (int off = 16; off >= 1; off >>= 1)
#pragma unroll
        for (int d = 0; d < 16; d++) s[d] += __shfl_down_sync(0xffffffffu, s[d], off);
    if (lane == 0)
#pragma unroll
        for (int d = 0; d < 16; d++) red[warp * 20 + d] = s[d];
    __syncthreads();
    if (t < 16) {
        float ss = 0.f;
#pragma unroll
        for (int w = 0; w < 8; w++) ss += red[w * 20 + t];
        fin[t] = ss;
    }
    __syncthreads();

    // v1 = squash(mean_i u) — computed redundantly by all threads into registers
    float v[16];
    {
        float sq = 0.f;
#pragma unroll
        for (int d = 0; d < 16; d++) {
            float sd = fin[d] * (1.0f / (float)NIC);
            v[d] = sd;
            sq += sd * sd;
        }
        float scale = sq / ((1.0f + sq) * sqrtf(sq + 1e-9f));
#pragma unroll
        for (int d = 0; d < 16; d++) v[d] *= scale;
    }

    float bl[8];
#pragma unroll
    for (int k = 0; k < 8; k++) bl[k] = 0.f;

    __syncthreads();   // slice fully staged before scan phase (also red/fin reuse)

    // ---- iterations 2 and 3: one fused SMEM scan each ----
#pragma unroll
    for (int iter = 0; iter < 2; iter++) {
#pragma unroll
        for (int d = 0; d < 16; d++) s[d] = 0.f;
        float Z = 0.f;
#pragma unroll
        for (int k = 0; k < 8; k++) {
            const __half* row = &su[(t + 256 * k) * ROWH];
            uint4 r0 = *(const uint4*)(row);
            uint4 r1 = *(const uint4*)(row + 8);
            const __half2* h0 = (const __half2*)&r0;
            const __half2* h1 = (const __half2*)&r1;
            float uf[16];
#pragma unroll
            for (int p = 0; p < 4; p++) {
                float2 f0 = __half22float2(h0[p]);
                float2 f1 = __half22float2(h1[p]);
                uf[2 * p]         = f0.x;
                uf[2 * p + 1]     = f0.y;
                uf[8 + 2 * p]     = f1.x;
                uf[8 + 2 * p + 1] = f1.y;
            }
            float dot = 0.f;
#pragma unroll
            for (int d = 0; d < 16; d++) dot += uf[d] * v[d];
            float b = bl[k] + dot;
            bl[k] = b;
            float e = __expf(b);   // b-logits bounded ~|1|, no max-subtraction needed
            Z += e;
#pragma unroll
            for (int d = 0; d < 16; d++) s[d] += e * uf[d];
        }
        // block reduce 17 values
#pragma unroll
        for (int off = 16; off >= 1; off >>= 1) {
#pragma unroll
            for (int d = 0; d < 16; d++) s[d] += __shfl_down_sync(0xffffffffu, s[d], off);
            Z += __shfl_down_sync(0xffffffffu, Z, off);
        }
        if (lane == 0) {
#pragma unroll
            for (int d = 0; d < 16; d++) red[warp * 20 + d] = s[d];
            red[warp * 20 + 16] = Z;
        }
        __syncthreads();
        if (t < 17) {
            float ss = 0.f;
#pragma unroll
            for (int w = 0; w < 8; w++) ss += red[w * 20 + t];
            fin[t] = ss;
        }
        __syncthreads();

        float inv = 1.0f / fin[16];
        float sq = 0.f;
        float sloc[16];
#pragma unroll
        for (int d = 0; d < 16; d++) {
            sloc[d] = fin[d] * inv;
            sq += sloc[d] * sloc[d];
        }
        float scale = sq / ((1.0f + sq) * sqrtf(sq + 1e-9f));
        if (iter == 1) {
            if (t < 16) out[bo * 16 + t] = sloc[t] * scale;
        } else {
#pragma unroll
            for (int d = 0; d < 16; d++) v[d] = sloc[d] * scale;
        }
        __syncthreads();
    }
}

// ---------------------------------------------------------------------------
extern "C" void kernel_launch(void* const* d_in, const int* in_sizes, int n_in,
                              void* d_out, int out_size) {
    (void)in_sizes; (void)n_in; (void)out_size;
    const float* x = (const float*)d_in[0];   // [64, 2048, 8]
    const float* W = (const float*)d_in[1];   // [1, 2048, 32, 16, 8]
    float* out = (float*)d_out;               // [64, 32, 16]

    uhat_kernel<<<dim3(NIC / 64, NOC), 256>>>(x, W);

    const int smem = NIC * ROWH * (int)sizeof(__half);   // 98304 B
    cudaFuncSetAttribute(route_kernel, cudaFuncAttributeMaxDynamicSharedMemorySize, smem);
    route_kernel<<<NB * NOC, 256, smem>>>(out);
}